// round 3
// baseline (speedup 1.0000x reference)
#include <cuda_runtime.h>
#include <cuda_fp16.h>
#include <math.h>
#include <stdint.h>

// ---------------------------------------------------------------------------
// Problem constants
// ---------------------------------------------------------------------------
#define BB   16
#define NN   512
#define DIM  256
#define NH   8
#define HD   32
#define ROWS (BB*NN)          // 8192
#define MAXD 128
#define NG   32

// scratch layout (floats). bias is __half (33554432 halves = 16777216 floats)
#define OFF_BIAS 0
#define OFF_H    16777216                  // ln1 out   [8192,256]
#define OFF_QKV  (OFF_H    + 2097152)      // [8192,768]
#define OFF_CTX  (OFF_QKV  + 6291456)      // [8192,256]
#define OFF_HATT (OFF_CTX  + 2097152)      // [8192,256]
#define OFF_H2   (OFF_HATT + 2097152)      // [8192,256]
#define OFF_F1   (OFF_H2   + 2097152)      // [8192,1024]
#define SCRATCH_FLOATS (OFF_F1 + 8388608)

__device__ float g_scratch[SCRATCH_FLOATS];

// ---------------------------------------------------------------------------
// helpers
// ---------------------------------------------------------------------------
__device__ __forceinline__ uint32_t f2tf32(float x) {
    uint32_t r;
    asm("cvt.rna.tf32.f32 %0, %1;" : "=r"(r) : "f"(x));
    return r;
}

__device__ __forceinline__ void cp16(void* s, const void* g) {
    unsigned sa = (unsigned)__cvta_generic_to_shared(s);
    asm volatile("cp.async.cg.shared.global [%0], [%1], 16;" :: "r"(sa), "l"(g));
}
#define CP_COMMIT() asm volatile("cp.async.commit_group;")

__device__ __forceinline__ void mma_tf32(float& d0, float& d1, float& d2, float& d3,
                                         uint32_t a0, uint32_t a1, uint32_t a2, uint32_t a3,
                                         uint32_t b0, uint32_t b1) {
    asm volatile(
        "mma.sync.aligned.m16n8k8.row.col.f32.tf32.tf32.f32 "
        "{%0,%1,%2,%3}, {%4,%5,%6,%7}, {%8,%9}, {%0,%1,%2,%3};\n"
        : "+f"(d0), "+f"(d1), "+f"(d2), "+f"(d3)
        : "r"(a0), "r"(a1), "r"(a2), "r"(a3), "r"(b0), "r"(b1));
}

// ---------------------------------------------------------------------------
// LayerNorm: one block per row (256 threads, 1 elem/thread)
// ---------------------------------------------------------------------------
__global__ void ln_kernel(const float* __restrict__ x,
                          const float* __restrict__ g,
                          const float* __restrict__ be,
                          float* __restrict__ out) {
    int row = blockIdx.x;
    int t   = threadIdx.x;
    float v = x[row * DIM + t];

    float s = v, sq = v * v;
    #pragma unroll
    for (int off = 16; off; off >>= 1) {
        s  += __shfl_xor_sync(0xffffffffu, s,  off);
        sq += __shfl_xor_sync(0xffffffffu, sq, off);
    }
    __shared__ float rs[8], rq[8];
    int warp = t >> 5, lane = t & 31;
    if (lane == 0) { rs[warp] = s; rq[warp] = sq; }
    __syncthreads();
    float ts = 0.f, tq = 0.f;
    #pragma unroll
    for (int w = 0; w < 8; w++) { ts += rs[w]; tq += rq[w]; }

    float mean = ts * (1.0f / DIM);
    float var  = tq * (1.0f / DIM) - mean * mean;
    float inv  = rsqrtf(var + 1e-5f);
    out[row * DIM + t] = (v - mean) * inv * g[t] + be[t];
}

// ---------------------------------------------------------------------------
// Bias kernel -> __half bias[b,h,q,k]
// one block per (b,q), thread t handles k = 2t, 2t+1
// ---------------------------------------------------------------------------
__global__ void bias_kernel(const int*   __restrict__ dm,
                            const float* __restrict__ d3,
                            const float* __restrict__ dist_emb,
                            const float* __restrict__ rbf_w,
                            const float* __restrict__ rbf_b,
                            __half* __restrict__ bias) {
    int bq = blockIdx.x;            // 0..8191
    int b  = bq >> 9;
    int q  = bq & 511;
    int t  = threadIdx.x;

    __shared__ float w_s[NH * NG];
    __shared__ float b_s[NH];
    __shared__ float emb_s[MAXD * NH];
    if (t < NH * NG) w_s[t] = rbf_w[t];
    if (t < NH)      b_s[t] = rbf_b[t];
    for (int i = t; i < MAXD * NH; i += 256) emb_s[i] = dist_emb[i];
    __syncthreads();

    const float step  = 20.0f / 31.0f;
    const float coeff = -0.5f / (step * step);
    size_t base = (size_t)bq * NN;

    int k = t * 2;
    float dd0 = d3[base + k],     dd1 = d3[base + k + 1];
    int   di0 = dm[base + k],     di1 = dm[base + k + 1];
    di0 = min(max(di0, 0), MAXD - 1);
    di1 = min(max(di1, 0), MAXD - 1);

    float r0[NG], r1[NG];
    #pragma unroll
    for (int gg = 0; gg < NG; gg++) {
        float c  = (float)gg * step;
        float f0 = dd0 - c, f1 = dd1 - c;
        r0[gg] = __expf(coeff * f0 * f0);
        r1[gg] = __expf(coeff * f1 * f1);
    }
    #pragma unroll
    for (int h = 0; h < NH; h++) {
        float a0 = b_s[h] + emb_s[di0 * NH + h];
        float a1 = b_s[h] + emb_s[di1 * NH + h];
        #pragma unroll
        for (int gg = 0; gg < NG; gg++) {
            float w = w_s[h * NG + gg];
            a0 += r0[gg] * w;
            a1 += r1[gg] * w;
        }
        size_t idx = ((size_t)(b * NH + h) * NN + q) * NN + k;
        *(__half2*)&bias[idx] = __floats2half2_rn(a0, a1);
    }
}

// ---------------------------------------------------------------------------
// Flash attention (fp32 math, __half bias): block = (q-tile 64, head, batch)
// ---------------------------------------------------------------------------
__global__ void attn_kernel(const float* __restrict__ qkv,
                            const __half* __restrict__ bias,
                            float* __restrict__ ctx) {
    const int qt = blockIdx.x;   // 0..7
    const int h  = blockIdx.y;   // 0..7
    const int b  = blockIdx.z;   // 0..15
    const int q0 = qt * 64;
    const int t  = threadIdx.x;

    __shared__ float Qs[64][33];
    __shared__ float Ks[64][33];
    __shared__ float Vs[64][32];
    __shared__ float S [64][65];
    __shared__ float m_row[64], l_row[64], f_row[64];

    const int d  = t & 31;
    const int iw = t >> 5;
    const int lane = t & 31;

    #pragma unroll
    for (int j = 0; j < 8; j++) {
        int i = iw + j * 8;
        Qs[i][d] = qkv[(size_t)(b * NN + q0 + i) * 768 + h * HD + d];
    }
    if (t < 64) { m_row[t] = -1e30f; l_row[t] = 0.f; f_row[t] = 0.f; }

    const int si = (t >> 4) * 4;
    const int sj = (t & 15) * 4;
    const int qp = (t >> 4) * 4;
    const int d2 = (t & 15) * 2;
    float acc[4][2] = {};
    const float scale = 0.17677669529663687f; // 1/sqrt(32)

    for (int kt = 0; kt < 8; kt++) {
        int k0 = kt * 64;
        __syncthreads();
        #pragma unroll
        for (int j = 0; j < 8; j++) {
            int i = iw + j * 8;
            size_t base = (size_t)(b * NN + k0 + i) * 768 + h * HD + d;
            Ks[i][d] = qkv[base + 256];
            Vs[i][d] = qkv[base + 512];
        }
        __syncthreads();

        float s4[4][4] = {};
        #pragma unroll
        for (int dd = 0; dd < 32; dd++) {
            float a0 = Qs[si + 0][dd], a1 = Qs[si + 1][dd];
            float a2 = Qs[si + 2][dd], a3 = Qs[si + 3][dd];
            float b0 = Ks[sj + 0][dd], b1 = Ks[sj + 1][dd];
            float b2 = Ks[sj + 2][dd], b3 = Ks[sj + 3][dd];
            s4[0][0] += a0 * b0; s4[0][1] += a0 * b1; s4[0][2] += a0 * b2; s4[0][3] += a0 * b3;
            s4[1][0] += a1 * b0; s4[1][1] += a1 * b1; s4[1][2] += a1 * b2; s4[1][3] += a1 * b3;
            s4[2][0] += a2 * b0; s4[2][1] += a2 * b1; s4[2][2] += a2 * b2; s4[2][3] += a2 * b3;
            s4[3][0] += a3 * b0; s4[3][1] += a3 * b1; s4[3][2] += a3 * b2; s4[3][3] += a3 * b3;
        }
        #pragma unroll
        for (int r = 0; r < 4; r++) {
            const __half2* bp = (const __half2*)&bias[
                ((size_t)(b * NH + h) * NN + (q0 + si + r)) * NN + k0 + sj];
            float2 f01 = __half22float2(bp[0]);
            float2 f23 = __half22float2(bp[1]);
            S[si + r][sj + 0] = s4[r][0] * scale + f01.x;
            S[si + r][sj + 1] = s4[r][1] * scale + f01.y;
            S[si + r][sj + 2] = s4[r][2] * scale + f23.x;
            S[si + r][sj + 3] = s4[r][3] * scale + f23.y;
        }
        __syncthreads();

        #pragma unroll
        for (int rr = 0; rr < 8; rr++) {
            int row = iw * 8 + rr;
            float v0 = S[row][lane * 2], v1 = S[row][lane * 2 + 1];
            float mx = fmaxf(v0, v1);
            #pragma unroll
            for (int off = 16; off; off >>= 1)
                mx = fmaxf(mx, __shfl_xor_sync(0xffffffffu, mx, off));
            float mo = m_row[row];
            float mn = fmaxf(mo, mx);
            float p0 = __expf(v0 - mn), p1 = __expf(v1 - mn);
            S[row][lane * 2] = p0; S[row][lane * 2 + 1] = p1;
            float ls = p0 + p1;
            #pragma unroll
            for (int off = 16; off; off >>= 1)
                ls += __shfl_xor_sync(0xffffffffu, ls, off);
            if (lane == 0) {
                float f = __expf(mo - mn);
                m_row[row] = mn;
                l_row[row] = l_row[row] * f + ls;
                f_row[row] = f;
            }
        }
        __syncthreads();

        #pragma unroll
        for (int r = 0; r < 4; r++) {
            float f = f_row[qp + r];
            acc[r][0] *= f; acc[r][1] *= f;
        }
        for (int k = 0; k < 64; k++) {
            float2 vv = *(const float2*)&Vs[k][d2];
            #pragma unroll
            for (int r = 0; r < 4; r++) {
                float p = S[qp + r][k];
                acc[r][0] += p * vv.x;
                acc[r][1] += p * vv.y;
            }
        }
    }

    #pragma unroll
    for (int r = 0; r < 4; r++) {
        int row = qp + r;
        float inv = 1.0f / l_row[row];
        float2 o;
        o.x = acc[r][0] * inv;
        o.y = acc[r][1] * inv;
        *(float2*)&ctx[(size_t)(b * NN + q0 + row) * DIM + h * HD + d2] = o;
    }
}

// ---------------------------------------------------------------------------
// TF32 tensor-core GEMM: C[M,Nn] = A[M,K] @ Bw[Nn,K]^T + bias (+gelu)(+res)
// Block tile 128x128x32, 256 threads (8 warps 2x4), warp tile 64x32,
// mma.m16n8k8.tf32, cp.async double buffered.
// smem row stride 36 floats (=144B, 16B aligned, conflict-free fragments).
// ---------------------------------------------------------------------------
#define GSTRIDE 36
#define GTILE   (128 * GSTRIDE)

template<bool GELU, bool RES>
__global__ __launch_bounds__(256, 2)
void tf32_gemm(const float* __restrict__ A,
               const float* __restrict__ Bw,
               const float* __restrict__ bias,
               const float* __restrict__ res,
               float* __restrict__ C,
               int Nn, int K) {
    extern __shared__ float smem[];
    float* As = smem;               // [2][128][36]
    float* Bs = smem + 2 * GTILE;   // [2][128][36]

    const int t    = threadIdx.x;
    const int bm   = blockIdx.x * 128;
    const int bn   = blockIdx.y * 128;
    const int wid  = t >> 5;
    const int lane = t & 31;
    const int wm   = (wid >> 2) * 64;   // 0 or 64
    const int wn   = (wid & 3) * 32;    // 0,32,64,96
    const int g    = lane >> 2;         // 0..7
    const int tt   = lane & 3;          // 0..3

    // global loader mapping: 256 threads x 4 rows, 16B per row-segment
    const int lrow = t >> 3;            // 0..31
    const int lc4  = (t & 7) * 4;       // 0..28

    float acc[4][4][4];
    #pragma unroll
    for (int i = 0; i < 4; i++)
        #pragma unroll
        for (int j = 0; j < 4; j++)
            #pragma unroll
            for (int c = 0; c < 4; c++) acc[i][j][c] = 0.f;

    const int niter = K >> 5;

    // prologue: stage 0
    {
        #pragma unroll
        for (int i = 0; i < 4; i++) {
            int row = lrow + i * 32;
            cp16(&As[row * GSTRIDE + lc4], &A[(size_t)(bm + row) * K + lc4]);
            cp16(&Bs[row * GSTRIDE + lc4], &Bw[(size_t)(bn + row) * K + lc4]);
        }
        CP_COMMIT();
    }

    for (int it = 0; it < niter; it++) {
        if (it + 1 < niter) {
            int buf = (it + 1) & 1;
            int k0  = (it + 1) * 32;
            #pragma unroll
            for (int i = 0; i < 4; i++) {
                int row = lrow + i * 32;
                cp16(&As[buf * GTILE + row * GSTRIDE + lc4], &A[(size_t)(bm + row) * K + k0 + lc4]);
                cp16(&Bs[buf * GTILE + row * GSTRIDE + lc4], &Bw[(size_t)(bn + row) * K + k0 + lc4]);
            }
            CP_COMMIT();
            asm volatile("cp.async.wait_group 1;");
        } else {
            asm volatile("cp.async.wait_group 0;");
        }
        __syncthreads();

        const float* Ab = As + (it & 1) * GTILE;
        const float* Bb = Bs + (it & 1) * GTILE;

        #pragma unroll
        for (int s = 0; s < 4; s++) {
            int c = s * 8 + tt;
            uint32_t af[4][4];
            #pragma unroll
            for (int mt = 0; mt < 4; mt++) {
                int r0 = wm + mt * 16 + g;
                af[mt][0] = f2tf32(Ab[(r0    ) * GSTRIDE + c    ]);
                af[mt][1] = f2tf32(Ab[(r0 + 8) * GSTRIDE + c    ]);
                af[mt][2] = f2tf32(Ab[(r0    ) * GSTRIDE + c + 4]);
                af[mt][3] = f2tf32(Ab[(r0 + 8) * GSTRIDE + c + 4]);
            }
            uint32_t bf[4][2];
            #pragma unroll
            for (int nt = 0; nt < 4; nt++) {
                int n0 = wn + nt * 8 + g;
                bf[nt][0] = f2tf32(Bb[n0 * GSTRIDE + c    ]);
                bf[nt][1] = f2tf32(Bb[n0 * GSTRIDE + c + 4]);
            }
            #pragma unroll
            for (int mt = 0; mt < 4; mt++)
                #pragma unroll
                for (int nt = 0; nt < 4; nt++)
                    mma_tf32(acc[mt][nt][0], acc[mt][nt][1], acc[mt][nt][2], acc[mt][nt][3],
                             af[mt][0], af[mt][1], af[mt][2], af[mt][3],
                             bf[nt][0], bf[nt][1]);
        }
        __syncthreads();
    }

    // epilogue: c0:(g, 2tt) c1:(g, 2tt+1) c2:(g+8, 2tt) c3:(g+8, 2tt+1)
    #pragma unroll
    for (int mt = 0; mt < 4; mt++) {
        #pragma unroll
        for (int nt = 0; nt < 4; nt++) {
            int row0 = bm + wm + mt * 16 + g;
            int col  = bn + wn + nt * 8 + 2 * tt;
            float b0 = bias[col], b1 = bias[col + 1];

            float v00 = acc[mt][nt][0] + b0;
            float v01 = acc[mt][nt][1] + b1;
            float v10 = acc[mt][nt][2] + b0;
            float v11 = acc[mt][nt][3] + b1;
            if (GELU) {
                v00 = 0.5f * v00 * (1.0f + erff(v00 * 0.70710678118654752f));
                v01 = 0.5f * v01 * (1.0f + erff(v01 * 0.70710678118654752f));
                v10 = 0.5f * v10 * (1.0f + erff(v10 * 0.70710678118654752f));
                v11 = 0.5f * v11 * (1.0f + erff(v11 * 0.70710678118654752f));
            }
            if (RES) {
                float2 r0 = *(const float2*)&res[(size_t)row0 * Nn + col];
                float2 r1 = *(const float2*)&res[(size_t)(row0 + 8) * Nn + col];
                v00 += r0.x; v01 += r0.y;
                v10 += r1.x; v11 += r1.y;
            }
            float2 o0; o0.x = v00; o0.y = v01;
            float2 o1; o1.x = v10; o1.y = v11;
            *(float2*)&C[(size_t)row0 * Nn + col]       = o0;
            *(float2*)&C[(size_t)(row0 + 8) * Nn + col] = o1;
        }
    }
}

#define GEMM_SMEM (4 * GTILE * sizeof(float))   // 73728 B

// ---------------------------------------------------------------------------
// launch
// ---------------------------------------------------------------------------
extern "C" void kernel_launch(void* const* d_in, const int* in_sizes, int n_in,
                              void* d_out, int out_size) {
    const float* x    = (const float*)d_in[0];
    const int*   dm   = (const int*)  d_in[2];
    const float* d3   = (const float*)d_in[3];
    const float* n1g  = (const float*)d_in[4];
    const float* n1b  = (const float*)d_in[5];
    const float* ipw  = (const float*)d_in[6];
    const float* ipb  = (const float*)d_in[7];
    const float* opw  = (const float*)d_in[8];
    const float* opb  = (const float*)d_in[9];
    const float* demb = (const float*)d_in[10];
    const float* rbfw = (const float*)d_in[11];
    const float* rbfb = (const float*)d_in[12];
    const float* n2g  = (const float*)d_in[13];
    const float* n2b  = (const float*)d_in[14];
    const float* w1   = (const float*)d_in[15];
    const float* b1   = (const float*)d_in[16];
    const float* w2   = (const float*)d_in[17];
    const float* b2   = (const float*)d_in[18];
    float* out = (float*)d_out;

    float* scratch = nullptr;
    cudaGetSymbolAddress((void**)&scratch, g_scratch);
    __half* bias = (__half*)(scratch + OFF_BIAS);
    float* hs   = scratch + OFF_H;
    float* qkv  = scratch + OFF_QKV;
    float* ctx  = scratch + OFF_CTX;
    float* hatt = scratch + OFF_HATT;
    float* h2   = scratch + OFF_H2;
    float* f1   = scratch + OFF_F1;

    static bool attr_done = false;
    if (!attr_done) {
        cudaFuncSetAttribute(tf32_gemm<false, false>, cudaFuncAttributeMaxDynamicSharedMemorySize, GEMM_SMEM);
        cudaFuncSetAttribute(tf32_gemm<false, true >, cudaFuncAttributeMaxDynamicSharedMemorySize, GEMM_SMEM);
        cudaFuncSetAttribute(tf32_gemm<true,  false>, cudaFuncAttributeMaxDynamicSharedMemorySize, GEMM_SMEM);
        attr_done = true;
    }

    // 1. h = LN1(x)
    ln_kernel<<<ROWS, 256>>>(x, n1g, n1b, hs);
    // 2. qkv = h @ in_proj_w^T + b
    tf32_gemm<false, false><<<dim3(ROWS / 128, 768 / 128), 256, GEMM_SMEM>>>(hs, ipw, ipb, nullptr, qkv, 768, 256);
    // 3. bias[b,h,q,k] (half)
    bias_kernel<<<ROWS, 256>>>(dm, d3, demb, rbfw, rbfb, bias);
    // 4. attention -> ctx [B,N,DIM]
    attn_kernel<<<dim3(NN / 64, NH, BB), 256>>>(qkv, bias, ctx);
    // 5. hatt = ctx @ out_proj^T + b + h
    tf32_gemm<false, true><<<dim3(ROWS / 128, 256 / 128), 256, GEMM_SMEM>>>(ctx, opw, opb, hs, hatt, 256, 256);
    // 6. h2 = LN2(hatt)
    ln_kernel<<<ROWS, 256>>>(hatt, n2g, n2b, h2);
    // 7. f1 = gelu(h2 @ w1^T + b1)
    tf32_gemm<true, false><<<dim3(ROWS / 128, 1024 / 128), 256, GEMM_SMEM>>>(h2, w1, b1, nullptr, f1, 1024, 256);
    // 8. out = f1 @ w2^T + b2 + hatt
    tf32_gemm<false, true><<<dim3(ROWS / 128, 256 / 128), 256, GEMM_SMEM>>>(f1, w2, b2, hatt, out, 256, 1024);
}

// round 4
// speedup vs baseline: 1.5102x; 1.5102x over previous
#include <cuda_runtime.h>
#include <cuda_fp16.h>
#include <math.h>
#include <stdint.h>

// ---------------------------------------------------------------------------
// Problem constants
// ---------------------------------------------------------------------------
#define BB   16
#define NN   512
#define DIM  256
#define NH   8
#define HD   32
#define ROWS (BB*NN)          // 8192
#define MAXD 128
#define NG   32

// scratch layout (float units). bias: half[33554432] = 16777216 floats.
// qkv: half[8192*768] = 3145728 floats.
#define OFF_BIAS 0
#define OFF_H    16777216                  // ln1 out   [8192,256] f32
#define OFF_QKV  (OFF_H    + 2097152)      // [8192,768] half
#define OFF_CTX  (OFF_QKV  + 3145728)      // [8192,256] f32
#define OFF_HATT (OFF_CTX  + 2097152)      // [8192,256] f32
#define OFF_H2   (OFF_HATT + 2097152)      // [8192,256] f32
#define OFF_F1   (OFF_H2   + 2097152)      // [8192,1024] f32
#define SCRATCH_FLOATS (OFF_F1 + 8388608)

__device__ float g_scratch[SCRATCH_FLOATS];

// ---------------------------------------------------------------------------
// helpers
// ---------------------------------------------------------------------------
__device__ __forceinline__ uint32_t f2tf32(float x) {
    uint32_t r;
    asm("cvt.rna.tf32.f32 %0, %1;" : "=r"(r) : "f"(x));
    return r;
}

__device__ __forceinline__ void cp16(void* s, const void* g) {
    unsigned sa = (unsigned)__cvta_generic_to_shared(s);
    asm volatile("cp.async.cg.shared.global [%0], [%1], 16;" :: "r"(sa), "l"(g));
}
#define CP_COMMIT() asm volatile("cp.async.commit_group;")

__device__ __forceinline__ uint32_t smem_u32(const void* p) {
    return (uint32_t)__cvta_generic_to_shared(p);
}

__device__ __forceinline__ void mma_tf32(float& d0, float& d1, float& d2, float& d3,
                                         uint32_t a0, uint32_t a1, uint32_t a2, uint32_t a3,
                                         uint32_t b0, uint32_t b1) {
    asm volatile(
        "mma.sync.aligned.m16n8k8.row.col.f32.tf32.tf32.f32 "
        "{%0,%1,%2,%3}, {%4,%5,%6,%7}, {%8,%9}, {%0,%1,%2,%3};\n"
        : "+f"(d0), "+f"(d1), "+f"(d2), "+f"(d3)
        : "r"(a0), "r"(a1), "r"(a2), "r"(a3), "r"(b0), "r"(b1));
}

__device__ __forceinline__ void mma_f16(float* d, const uint32_t* a, uint32_t b0, uint32_t b1) {
    asm volatile(
        "mma.sync.aligned.m16n8k16.row.col.f32.f16.f16.f32 "
        "{%0,%1,%2,%3}, {%4,%5,%6,%7}, {%8,%9}, {%0,%1,%2,%3};\n"
        : "+f"(d[0]), "+f"(d[1]), "+f"(d[2]), "+f"(d[3])
        : "r"(a[0]), "r"(a[1]), "r"(a[2]), "r"(a[3]), "r"(b0), "r"(b1));
}

#define LDSM_X4(r0,r1,r2,r3,addr) \
    asm volatile("ldmatrix.sync.aligned.m8n8.x4.shared.b16 {%0,%1,%2,%3}, [%4];" \
        : "=r"(r0), "=r"(r1), "=r"(r2), "=r"(r3) : "r"(addr))
#define LDSM_X4_T(r0,r1,r2,r3,addr) \
    asm volatile("ldmatrix.sync.aligned.m8n8.x4.trans.shared.b16 {%0,%1,%2,%3}, [%4];" \
        : "=r"(r0), "=r"(r1), "=r"(r2), "=r"(r3) : "r"(addr))

__device__ __forceinline__ uint32_t packh2(float x, float y) {
    __half2 h = __floats2half2_rn(x, y);
    return *reinterpret_cast<uint32_t*>(&h);
}

// ---------------------------------------------------------------------------
// LayerNorm: one block per row (256 threads, 1 elem/thread)
// ---------------------------------------------------------------------------
__global__ void ln_kernel(const float* __restrict__ x,
                          const float* __restrict__ g,
                          const float* __restrict__ be,
                          float* __restrict__ out) {
    int row = blockIdx.x;
    int t   = threadIdx.x;
    float v = x[row * DIM + t];

    float s = v, sq = v * v;
    #pragma unroll
    for (int off = 16; off; off >>= 1) {
        s  += __shfl_xor_sync(0xffffffffu, s,  off);
        sq += __shfl_xor_sync(0xffffffffu, sq, off);
    }
    __shared__ float rs[8], rq[8];
    int warp = t >> 5, lane = t & 31;
    if (lane == 0) { rs[warp] = s; rq[warp] = sq; }
    __syncthreads();
    float ts = 0.f, tq = 0.f;
    #pragma unroll
    for (int w = 0; w < 8; w++) { ts += rs[w]; tq += rq[w]; }

    float mean = ts * (1.0f / DIM);
    float var  = tq * (1.0f / DIM) - mean * mean;
    float inv  = rsqrtf(var + 1e-5f);
    out[row * DIM + t] = (v - mean) * inv * g[t] + be[t];
}

// ---------------------------------------------------------------------------
// Bias kernel -> __half bias[b,h,q,k]; block=(b,q), thread t -> k=2t,2t+1
// ---------------------------------------------------------------------------
__global__ void bias_kernel(const int*   __restrict__ dm,
                            const float* __restrict__ d3,
                            const float* __restrict__ dist_emb,
                            const float* __restrict__ rbf_w,
                            const float* __restrict__ rbf_b,
                            __half* __restrict__ bias) {
    int bq = blockIdx.x;
    int b  = bq >> 9;
    int q  = bq & 511;
    int t  = threadIdx.x;

    __shared__ float w_s[NH * NG];
    __shared__ float b_s[NH];
    __shared__ float emb_s[MAXD * NH];
    if (t < NH * NG) w_s[t] = rbf_w[t];
    if (t < NH)      b_s[t] = rbf_b[t];
    for (int i = t; i < MAXD * NH; i += 256) emb_s[i] = dist_emb[i];
    __syncthreads();

    const float step  = 20.0f / 31.0f;
    const float coeff = -0.5f / (step * step);
    size_t base = (size_t)bq * NN;

    int k = t * 2;
    float dd0 = d3[base + k],     dd1 = d3[base + k + 1];
    int   di0 = dm[base + k],     di1 = dm[base + k + 1];
    di0 = min(max(di0, 0), MAXD - 1);
    di1 = min(max(di1, 0), MAXD - 1);

    float r0[NG], r1[NG];
    #pragma unroll
    for (int gg = 0; gg < NG; gg++) {
        float c  = (float)gg * step;
        float f0 = dd0 - c, f1 = dd1 - c;
        r0[gg] = __expf(coeff * f0 * f0);
        r1[gg] = __expf(coeff * f1 * f1);
    }
    #pragma unroll
    for (int h = 0; h < NH; h++) {
        float a0 = b_s[h] + emb_s[di0 * NH + h];
        float a1 = b_s[h] + emb_s[di1 * NH + h];
        #pragma unroll
        for (int gg = 0; gg < NG; gg++) {
            float w = w_s[h * NG + gg];
            a0 += r0[gg] * w;
            a1 += r1[gg] * w;
        }
        size_t idx = ((size_t)(b * NH + h) * NN + q) * NN + k;
        *(__half2*)&bias[idx] = __floats2half2_rn(a0, a1);
    }
}

// ---------------------------------------------------------------------------
// FP16 tensor-core flash attention (FA2).
// block = (q-tile 128, head, batch): grid (4, 8, 16), 256 threads (8 warps).
// Each warp owns 16 q-rows. K-tiles of 64 keys, cp.async double-buffered.
// Q already scaled by 1/sqrt(HD) in the QKV GEMM epilogue.
// ---------------------------------------------------------------------------
#define KVSTRIDE 40   // halves per row (32 + 8 pad) = 80 B

__global__ __launch_bounds__(256)
void attn_kernel(const __half* __restrict__ qkv,
                 const __half* __restrict__ bias,
                 float* __restrict__ ctx) {
    const int qt = blockIdx.x;   // 0..3
    const int h  = blockIdx.y;   // 0..7
    const int b  = blockIdx.z;   // 0..15
    const int q0 = qt * 128;
    const int t  = threadIdx.x;
    const int wid  = t >> 5;
    const int lane = t & 31;
    const int g  = lane >> 2;    // 0..7
    const int tt = lane & 3;     // 0..3
    const int wr = wid * 16;     // warp q-row base within q-tile

    __shared__ __align__(16) __half Qs[128 * KVSTRIDE];
    __shared__ __align__(16) __half Ks[2 * 64 * KVSTRIDE];
    __shared__ __align__(16) __half Vs[2 * 64 * KVSTRIDE];

    // Q tile: 128 rows x 64B = 512 x 16B, 2 per thread
    #pragma unroll
    for (int r = 0; r < 2; r++) {
        int id = t * 2 + r;
        int row = id >> 2, seg = id & 3;
        cp16(&Qs[row * KVSTRIDE + seg * 8],
             qkv + (size_t)(b * NN + q0 + row) * 768 + h * HD + seg * 8);
    }
    // K/V tile 0: 64 rows x 4 segs each
    {
        int row = t >> 2, seg = t & 3;
        size_t src = (size_t)(b * NN + row) * 768 + h * HD + seg * 8;
        cp16(&Ks[row * KVSTRIDE + seg * 8], qkv + src + 256);
        cp16(&Vs[row * KVSTRIDE + seg * 8], qkv + src + 512);
    }
    CP_COMMIT();

    float m0 = -1e30f, m1 = -1e30f, l0 = 0.f, l1 = 0.f;
    float O[4][4] = {};
    uint32_t qa[2][4];
    bool qloaded = false;

    const __half* bptr0 = bias + ((size_t)(b * NH + h) * NN + (q0 + wr + g)) * NN;
    const __half* bptr1 = bptr0 + 8 * (size_t)NN;

    for (int kt = 0; kt < 8; kt++) {
        int buf = kt & 1;
        if (kt + 1 < 8) {
            int nb = (kt + 1) & 1;
            int k0n = (kt + 1) * 64;
            int row = t >> 2, seg = t & 3;
            size_t src = (size_t)(b * NN + k0n + row) * 768 + h * HD + seg * 8;
            cp16(&Ks[nb * 64 * KVSTRIDE + row * KVSTRIDE + seg * 8], qkv + src + 256);
            cp16(&Vs[nb * 64 * KVSTRIDE + row * KVSTRIDE + seg * 8], qkv + src + 512);
            CP_COMMIT();
            asm volatile("cp.async.wait_group 1;");
        } else {
            asm volatile("cp.async.wait_group 0;");
        }
        __syncthreads();

        if (!qloaded) {
            qloaded = true;
            #pragma unroll
            for (int ks = 0; ks < 2; ks++) {
                uint32_t a = smem_u32(&Qs[(wr + (lane & 15)) * KVSTRIDE + ks * 16 + 8 * (lane >> 4)]);
                LDSM_X4(qa[ks][0], qa[ks][1], qa[ks][2], qa[ks][3], a);
            }
        }

        const __half* Kb = Ks + buf * 64 * KVSTRIDE;
        const __half* Vb = Vs + buf * 64 * KVSTRIDE;

        // ---- S = Q @ K^T : 8 n-tiles of 8 keys ----
        float S[8][4];
        #pragma unroll
        for (int nt = 0; nt < 8; nt++) { S[nt][0] = S[nt][1] = S[nt][2] = S[nt][3] = 0.f; }

        #pragma unroll
        for (int ks = 0; ks < 2; ks++) {
            #pragma unroll
            for (int p = 0; p < 4; p++) {
                int rowk = 16 * p + 8 * (lane >> 4) + (lane & 7);
                int colk = ks * 16 + 8 * ((lane >> 3) & 1);
                uint32_t b0, b1, b2, b3;
                LDSM_X4(b0, b1, b2, b3, smem_u32(&Kb[rowk * KVSTRIDE + colk]));
                mma_f16(S[2 * p],     qa[ks], b0, b1);
                mma_f16(S[2 * p + 1], qa[ks], b2, b3);
            }
        }

        // ---- + bias ----
        int k0 = kt * 64;
        #pragma unroll
        for (int nt = 0; nt < 8; nt++) {
            float2 f0 = __half22float2(*(const __half2*)(bptr0 + k0 + nt * 8 + 2 * tt));
            float2 f1 = __half22float2(*(const __half2*)(bptr1 + k0 + nt * 8 + 2 * tt));
            S[nt][0] += f0.x; S[nt][1] += f0.y;
            S[nt][2] += f1.x; S[nt][3] += f1.y;
        }

        // ---- online softmax (rows g and g+8 of this warp) ----
        float mx0 = -1e30f, mx1 = -1e30f;
        #pragma unroll
        for (int nt = 0; nt < 8; nt++) {
            mx0 = fmaxf(mx0, fmaxf(S[nt][0], S[nt][1]));
            mx1 = fmaxf(mx1, fmaxf(S[nt][2], S[nt][3]));
        }
        #pragma unroll
        for (int off = 1; off <= 2; off <<= 1) {
            mx0 = fmaxf(mx0, __shfl_xor_sync(0xffffffffu, mx0, off));
            mx1 = fmaxf(mx1, __shfl_xor_sync(0xffffffffu, mx1, off));
        }
        float mn0 = fmaxf(m0, mx0), mn1 = fmaxf(m1, mx1);
        float sc0 = __expf(m0 - mn0), sc1 = __expf(m1 - mn1);
        float ls0 = 0.f, ls1 = 0.f;
        #pragma unroll
        for (int nt = 0; nt < 8; nt++) {
            S[nt][0] = __expf(S[nt][0] - mn0);
            S[nt][1] = __expf(S[nt][1] - mn0);
            S[nt][2] = __expf(S[nt][2] - mn1);
            S[nt][3] = __expf(S[nt][3] - mn1);
            ls0 += S[nt][0] + S[nt][1];
            ls1 += S[nt][2] + S[nt][3];
        }
        #pragma unroll
        for (int off = 1; off <= 2; off <<= 1) {
            ls0 += __shfl_xor_sync(0xffffffffu, ls0, off);
            ls1 += __shfl_xor_sync(0xffffffffu, ls1, off);
        }
        m0 = mn0; m1 = mn1;
        l0 = l0 * sc0 + ls0;
        l1 = l1 * sc1 + ls1;
        #pragma unroll
        for (int nt = 0; nt < 4; nt++) {
            O[nt][0] *= sc0; O[nt][1] *= sc0;
            O[nt][2] *= sc1; O[nt][3] *= sc1;
        }

        // ---- O += P @ V : S accumulator layout == A fragment layout ----
        #pragma unroll
        for (int j = 0; j < 4; j++) {            // key k-steps of 16
            uint32_t pa[4];
            pa[0] = packh2(S[2 * j][0],     S[2 * j][1]);
            pa[1] = packh2(S[2 * j][2],     S[2 * j][3]);
            pa[2] = packh2(S[2 * j + 1][0], S[2 * j + 1][1]);
            pa[3] = packh2(S[2 * j + 1][2], S[2 * j + 1][3]);
            #pragma unroll
            for (int q2 = 0; q2 < 2; q2++) {     // hd n-tile pairs
                int rowv = j * 16 + (lane & 7) + 8 * ((lane >> 3) & 1);
                int colv = q2 * 16 + 8 * (lane >> 4);
                uint32_t b0, b1, b2, b3;
                LDSM_X4_T(b0, b1, b2, b3, smem_u32(&Vb[rowv * KVSTRIDE + colv]));
                mma_f16(O[2 * q2],     pa, b0, b1);
                mma_f16(O[2 * q2 + 1], pa, b2, b3);
            }
        }
        __syncthreads();   // protect K/V buffers before next overwrite
    }

    // ---- epilogue: normalize, write ctx [B,N,DIM] fp32 ----
    float inv0 = 1.0f / l0, inv1 = 1.0f / l1;
    #pragma unroll
    for (int nt = 0; nt < 4; nt++) {
        int col = h * HD + nt * 8 + 2 * tt;
        float2 o0, o1;
        o0.x = O[nt][0] * inv0; o0.y = O[nt][1] * inv0;
        o1.x = O[nt][2] * inv1; o1.y = O[nt][3] * inv1;
        *(float2*)&ctx[(size_t)(b * NN + q0 + wr + g)     * DIM + col] = o0;
        *(float2*)&ctx[(size_t)(b * NN + q0 + wr + g + 8) * DIM + col] = o1;
    }
}

// ---------------------------------------------------------------------------
// TF32 tensor-core GEMM: C = A[M,K] @ Bw[Nn,K]^T + bias (+gelu)(+res)
// Block 128x128x32, 256 threads, warp 64x32, mma.m16n8k8, double-buffered.
// OUTH: write __half output with Q-columns (col<256) scaled by qscale.
// ---------------------------------------------------------------------------
#define GSTRIDE 36
#define GTILE   (128 * GSTRIDE)

template<bool GELU, bool RES, bool OUTH>
__global__ __launch_bounds__(256, 2)
void tf32_gemm(const float* __restrict__ A,
               const float* __restrict__ Bw,
               const float* __restrict__ bias,
               const float* __restrict__ res,
               void* __restrict__ Cv,
               int Nn, int K, float qscale) {
    extern __shared__ float smem[];
    float* As = smem;
    float* Bs = smem + 2 * GTILE;

    const int t    = threadIdx.x;
    const int bm   = blockIdx.x * 128;
    const int bn   = blockIdx.y * 128;
    const int wid  = t >> 5;
    const int lane = t & 31;
    const int wm   = (wid >> 2) * 64;
    const int wn   = (wid & 3) * 32;
    const int g    = lane >> 2;
    const int tt   = lane & 3;

    const int lrow = t >> 3;
    const int lc4  = (t & 7) * 4;

    float acc[4][4][4];
    #pragma unroll
    for (int i = 0; i < 4; i++)
        #pragma unroll
        for (int j = 0; j < 4; j++)
            #pragma unroll
            for (int c = 0; c < 4; c++) acc[i][j][c] = 0.f;

    const int niter = K >> 5;

    #pragma unroll
    for (int i = 0; i < 4; i++) {
        int row = lrow + i * 32;
        cp16(&As[row * GSTRIDE + lc4], &A[(size_t)(bm + row) * K + lc4]);
        cp16(&Bs[row * GSTRIDE + lc4], &Bw[(size_t)(bn + row) * K + lc4]);
    }
    CP_COMMIT();

    for (int it = 0; it < niter; it++) {
        if (it + 1 < niter) {
            int buf = (it + 1) & 1;
            int k0  = (it + 1) * 32;
            #pragma unroll
            for (int i = 0; i < 4; i++) {
                int row = lrow + i * 32;
                cp16(&As[buf * GTILE + row * GSTRIDE + lc4], &A[(size_t)(bm + row) * K + k0 + lc4]);
                cp16(&Bs[buf * GTILE + row * GSTRIDE + lc4], &Bw[(size_t)(bn + row) * K + k0 + lc4]);
            }
            CP_COMMIT();
            asm volatile("cp.async.wait_group 1;");
        } else {
            asm volatile("cp.async.wait_group 0;");
        }
        __syncthreads();

        const float* Ab = As + (it & 1) * GTILE;
        const float* Bb = Bs + (it & 1) * GTILE;

        #pragma unroll
        for (int s = 0; s < 4; s++) {
            int c = s * 8 + tt;
            uint32_t af[4][4];
            #pragma unroll
            for (int mt = 0; mt < 4; mt++) {
                int r0 = wm + mt * 16 + g;
                af[mt][0] = f2tf32(Ab[(r0    ) * GSTRIDE + c    ]);
                af[mt][1] = f2tf32(Ab[(r0 + 8) * GSTRIDE + c    ]);
                af[mt][2] = f2tf32(Ab[(r0    ) * GSTRIDE + c + 4]);
                af[mt][3] = f2tf32(Ab[(r0 + 8) * GSTRIDE + c + 4]);
            }
            uint32_t bf[4][2];
            #pragma unroll
            for (int nt = 0; nt < 4; nt++) {
                int n0 = wn + nt * 8 + g;
                bf[nt][0] = f2tf32(Bb[n0 * GSTRIDE + c    ]);
                bf[nt][1] = f2tf32(Bb[n0 * GSTRIDE + c + 4]);
            }
            #pragma unroll
            for (int mt = 0; mt < 4; mt++)
                #pragma unroll
                for (int nt = 0; nt < 4; nt++)
                    mma_tf32(acc[mt][nt][0], acc[mt][nt][1], acc[mt][nt][2], acc[mt][nt][3],
                             af[mt][0], af[mt][1], af[mt][2], af[mt][3],
                             bf[nt][0], bf[nt][1]);
        }
        __syncthreads();
    }

    #pragma unroll
    for (int mt = 0; mt < 4; mt++) {
        #pragma unroll
        for (int nt = 0; nt < 4; nt++) {
            int row0 = bm + wm + mt * 16 + g;
            int col  = bn + wn + nt * 8 + 2 * tt;
            float b0 = bias[col], b1 = bias[col + 1];

            float v00 = acc[mt][nt][0] + b0;
            float v01 = acc[mt][nt][1] + b1;
            float v10 = acc[mt][nt][2] + b0;
            float v11 = acc[mt][nt][3] + b1;
            if (GELU) {
                v00 = 0.5f * v00 * (1.0f + erff(v00 * 0.70710678118654752f));
                v01 = 0.5f * v01 * (1.0f + erff(v01 * 0.70710678118654752f));
                v10 = 0.5f * v10 * (1.0f + erff(v10 * 0.70710678118654752f));
                v11 = 0.5f * v11 * (1.0f + erff(v11 * 0.70710678118654752f));
            }
            if (RES) {
                const float* res_p = res;
                float2 r0 = *(const float2*)&res_p[(size_t)row0 * Nn + col];
                float2 r1 = *(const float2*)&res_p[(size_t)(row0 + 8) * Nn + col];
                v00 += r0.x; v01 += r0.y;
                v10 += r1.x; v11 += r1.y;
            }
            if (OUTH) {
                float s = (col < DIM) ? qscale : 1.0f;   // scale Q columns only
                __half* C = (__half*)Cv;
                *(__half2*)&C[(size_t)row0 * Nn + col]       = __floats2half2_rn(v00 * s, v01 * s);
                *(__half2*)&C[(size_t)(row0 + 8) * Nn + col] = __floats2half2_rn(v10 * s, v11 * s);
            } else {
                float* C = (float*)Cv;
                float2 o0; o0.x = v00; o0.y = v01;
                float2 o1; o1.x = v10; o1.y = v11;
                *(float2*)&C[(size_t)row0 * Nn + col]       = o0;
                *(float2*)&C[(size_t)(row0 + 8) * Nn + col] = o1;
            }
        }
    }
}

#define GEMM_SMEM (4 * GTILE * sizeof(float))   // 73728 B

// ---------------------------------------------------------------------------
// launch
// ---------------------------------------------------------------------------
extern "C" void kernel_launch(void* const* d_in, const int* in_sizes, int n_in,
                              void* d_out, int out_size) {
    const float* x    = (const float*)d_in[0];
    const int*   dm   = (const int*)  d_in[2];
    const float* d3   = (const float*)d_in[3];
    const float* n1g  = (const float*)d_in[4];
    const float* n1b  = (const float*)d_in[5];
    const float* ipw  = (const float*)d_in[6];
    const float* ipb  = (const float*)d_in[7];
    const float* opw  = (const float*)d_in[8];
    const float* opb  = (const float*)d_in[9];
    const float* demb = (const float*)d_in[10];
    const float* rbfw = (const float*)d_in[11];
    const float* rbfb = (const float*)d_in[12];
    const float* n2g  = (const float*)d_in[13];
    const float* n2b  = (const float*)d_in[14];
    const float* w1   = (const float*)d_in[15];
    const float* b1   = (const float*)d_in[16];
    const float* w2   = (const float*)d_in[17];
    const float* b2   = (const float*)d_in[18];
    float* out = (float*)d_out;

    float* scratch = nullptr;
    cudaGetSymbolAddress((void**)&scratch, g_scratch);
    __half* bias = (__half*)(scratch + OFF_BIAS);
    float*  hs   = scratch + OFF_H;
    __half* qkv  = (__half*)(scratch + OFF_QKV);
    float*  ctx  = scratch + OFF_CTX;
    float*  hatt = scratch + OFF_HATT;
    float*  h2   = scratch + OFF_H2;
    float*  f1   = scratch + OFF_F1;

    static bool attr_done = false;
    if (!attr_done) {
        cudaFuncSetAttribute(tf32_gemm<false, false, true >, cudaFuncAttributeMaxDynamicSharedMemorySize, GEMM_SMEM);
        cudaFuncSetAttribute(tf32_gemm<false, true,  false>, cudaFuncAttributeMaxDynamicSharedMemorySize, GEMM_SMEM);
        cudaFuncSetAttribute(tf32_gemm<true,  false, false>, cudaFuncAttributeMaxDynamicSharedMemorySize, GEMM_SMEM);
        attr_done = true;
    }

    const float qscale = 0.17677669529663687f;  // 1/sqrt(32)

    // 1. h = LN1(x)
    ln_kernel<<<ROWS, 256>>>(x, n1g, n1b, hs);
    // 2. qkv = h @ in_proj_w^T + b  (half output, Q pre-scaled)
    tf32_gemm<false, false, true><<<dim3(ROWS / 128, 768 / 128), 256, GEMM_SMEM>>>(
        hs, ipw, ipb, nullptr, qkv, 768, 256, qscale);
    // 3. bias[b,h,q,k] (half)
    bias_kernel<<<ROWS, 256>>>(dm, d3, demb, rbfw, rbfb, bias);
    // 4. attention -> ctx [B,N,DIM] fp32
    attn_kernel<<<dim3(NN / 128, NH, BB), 256>>>(qkv, bias, ctx);
    // 5. hatt = ctx @ out_proj^T + b + h
    tf32_gemm<false, true, false><<<dim3(ROWS / 128, 256 / 128), 256, GEMM_SMEM>>>(
        ctx, opw, opb, hs, hatt, 256, 256, 1.0f);
    // 6. h2 = LN2(hatt)
    ln_kernel<<<ROWS, 256>>>(hatt, n2g, n2b, h2);
    // 7. f1 = gelu(h2 @ w1^T + b1)
    tf32_gemm<true, false, false><<<dim3(ROWS / 128, 1024 / 128), 256, GEMM_SMEM>>>(
        h2, w1, b1, nullptr, f1, 1024, 256, 1.0f);
    // 8. out = f1 @ w2^T + b2 + hatt
    tf32_gemm<false, true, false><<<dim3(ROWS / 128, 256 / 128), 256, GEMM_SMEM>>>(
        f1, w2, b2, hatt, out, 256, 1024, 1.0f);
}

// round 5
// speedup vs baseline: 2.3932x; 1.5847x over previous
#include <cuda_runtime.h>
#include <cuda_fp16.h>
#include <math.h>
#include <stdint.h>

// ---------------------------------------------------------------------------
// Problem constants
// ---------------------------------------------------------------------------
#define BB   16
#define NN   512
#define DIM  256
#define NH   8
#define HD   32
#define ROWS (BB*NN)          // 8192
#define MAXD 128
#define NG   32

// scratch layout (float units)
#define OFF_BIAS 0                           // half [16*8*512*512] = 16777216 f
#define OFF_HS32 16777216                    // ln1 out f32 [8192,256]
#define OFF_HSH  (OFF_HS32 + 2097152)        // ln1 out half
#define OFF_QKV  (OFF_HSH  + 1048576)        // half [8192,768]
#define OFF_CTXH (OFF_QKV  + 3145728)        // half [8192,256]
#define OFF_HATT (OFF_CTXH + 1048576)        // f32  [8192,256]
#define OFF_H2H  (OFF_HATT + 2097152)        // half [8192,256]
#define OFF_F1H  (OFF_H2H  + 1048576)        // half [8192,1024]
#define OFF_WH   (OFF_F1H  + 4194304)        // half weights (786432 halves)
#define SCRATCH_FLOATS (OFF_WH + 393216)

__device__ float g_scratch[SCRATCH_FLOATS];

// half-weight sub-offsets (half units within OFF_WH)
#define WH_IPW 0
#define WH_OPW 196608
#define WH_W1  262144
#define WH_W2  524288

// ---------------------------------------------------------------------------
// helpers
// ---------------------------------------------------------------------------
__device__ __forceinline__ void cp16(void* s, const void* g) {
    unsigned sa = (unsigned)__cvta_generic_to_shared(s);
    asm volatile("cp.async.cg.shared.global [%0], [%1], 16;" :: "r"(sa), "l"(g));
}
#define CP_COMMIT() asm volatile("cp.async.commit_group;")

__device__ __forceinline__ uint32_t smem_u32(const void* p) {
    return (uint32_t)__cvta_generic_to_shared(p);
}

__device__ __forceinline__ void mma_f16(float* d, const uint32_t* a, uint32_t b0, uint32_t b1) {
    asm volatile(
        "mma.sync.aligned.m16n8k16.row.col.f32.f16.f16.f32 "
        "{%0,%1,%2,%3}, {%4,%5,%6,%7}, {%8,%9}, {%0,%1,%2,%3};\n"
        : "+f"(d[0]), "+f"(d[1]), "+f"(d[2]), "+f"(d[3])
        : "r"(a[0]), "r"(a[1]), "r"(a[2]), "r"(a[3]), "r"(b0), "r"(b1));
}

#define LDSM_X4(r0,r1,r2,r3,addr) \
    asm volatile("ldmatrix.sync.aligned.m8n8.x4.shared.b16 {%0,%1,%2,%3}, [%4];" \
        : "=r"(r0), "=r"(r1), "=r"(r2), "=r"(r3) : "r"(addr))
#define LDSM_X4_T(r0,r1,r2,r3,addr) \
    asm volatile("ldmatrix.sync.aligned.m8n8.x4.trans.shared.b16 {%0,%1,%2,%3}, [%4];" \
        : "=r"(r0), "=r"(r1), "=r"(r2), "=r"(r3) : "r"(addr))

__device__ __forceinline__ uint32_t packh2(float x, float y) {
    __half2 h = __floats2half2_rn(x, y);
    return *reinterpret_cast<uint32_t*>(&h);
}

// ---------------------------------------------------------------------------
// weight fp32 -> fp16 conversion (once per launch; 393216 half2)
// ---------------------------------------------------------------------------
__global__ void convert_w(const float* __restrict__ ipw, const float* __restrict__ opw,
                          const float* __restrict__ w1,  const float* __restrict__ w2,
                          __half2* __restrict__ wh) {
    int i = blockIdx.x * 256 + threadIdx.x;       // half2 index, 0..393215
    const int n0 = 98304, n1 = 32768, n2 = 131072;  // h2 counts
    float2 v;
    if (i < n0)                 v = ((const float2*)ipw)[i];
    else if (i < n0 + n1)       v = ((const float2*)opw)[i - n0];
    else if (i < n0 + n1 + n2)  v = ((const float2*)w1)[i - n0 - n1];
    else                        v = ((const float2*)w2)[i - n0 - n1 - n2];
    wh[i] = __floats2half2_rn(v.x, v.y);
}

// ---------------------------------------------------------------------------
// LayerNorm: writes half (GEMM A input) and optional fp32 (residual)
// ---------------------------------------------------------------------------
__global__ void ln_kernel(const float* __restrict__ x,
                          const float* __restrict__ g,
                          const float* __restrict__ be,
                          __half* __restrict__ out_h,
                          float* __restrict__ out_f) {
    int row = blockIdx.x;
    int t   = threadIdx.x;
    float v = x[row * DIM + t];

    float s = v, sq = v * v;
    #pragma unroll
    for (int off = 16; off; off >>= 1) {
        s  += __shfl_xor_sync(0xffffffffu, s,  off);
        sq += __shfl_xor_sync(0xffffffffu, sq, off);
    }
    __shared__ float rs[8], rq[8];
    int warp = t >> 5, lane = t & 31;
    if (lane == 0) { rs[warp] = s; rq[warp] = sq; }
    __syncthreads();
    float ts = 0.f, tq = 0.f;
    #pragma unroll
    for (int w = 0; w < 8; w++) { ts += rs[w]; tq += rq[w]; }

    float mean = ts * (1.0f / DIM);
    float var  = tq * (1.0f / DIM) - mean * mean;
    float inv  = rsqrtf(var + 1e-5f);
    float val  = (v - mean) * inv * g[t] + be[t];
    out_h[row * DIM + t] = __float2half(val);
    if (out_f) out_f[row * DIM + t] = val;
}

// ---------------------------------------------------------------------------
// Bias kernel (windowed 9-term Gaussian, half2 head-pair accumulation)
// block = (b,q); thread t -> k = 2t, 2t+1
// ---------------------------------------------------------------------------
__global__ void bias_kernel(const int*   __restrict__ dm,
                            const float* __restrict__ d3,
                            const float* __restrict__ dist_emb,
                            const float* __restrict__ rbf_w,
                            const float* __restrict__ rbf_b,
                            __half* __restrict__ bias) {
    int bq = blockIdx.x;
    int b  = bq >> 9;
    int q  = bq & 511;
    int t  = threadIdx.x;

    // w2_s[g*5+p] = (rbf_w[2p][g], rbf_w[2p+1][g]); stride 5 -> spread banks
    __shared__ __half2 w2_s[NG * 5];
    __shared__ __half2 eb_s[MAXD * 4];  // eb_s[d*4+p] = emb[d][2p..2p+1] + rbf_b
    if (t < 128) {
        int g = t >> 2, p = t & 3;
        w2_s[g * 5 + p] = __floats2half2_rn(rbf_w[(2 * p) * NG + g],
                                            rbf_w[(2 * p + 1) * NG + g]);
    }
    for (int i = t; i < MAXD * 4; i += 256) {
        int d = i >> 2, p = i & 3;
        eb_s[i] = __floats2half2_rn(dist_emb[d * NH + 2 * p]     + rbf_b[2 * p],
                                    dist_emb[d * NH + 2 * p + 1] + rbf_b[2 * p + 1]);
    }
    __syncthreads();

    const float invstep = 31.0f / 20.0f;
    size_t base = (size_t)bq * NN;
    int k = t * 2;

    float u0 = d3[base + k]     * invstep;
    float u1 = d3[base + k + 1] * invstep;
    int di0 = min(max(dm[base + k],     0), MAXD - 1);
    int di1 = min(max(dm[base + k + 1], 0), MAXD - 1);
    int g00 = __float2int_rn(u0);
    int g01 = __float2int_rn(u1);

    __half2 acc0[4], acc1[4];
    #pragma unroll
    for (int p = 0; p < 4; p++) { acc0[p] = eb_s[di0 * 4 + p]; acc1[p] = eb_s[di1 * 4 + p]; }

    #pragma unroll
    for (int j = 0; j < 9; j++) {
        int ga = g00 - 4 + j;
        int gb = g01 - 4 + j;
        float dua = u0 - (float)ga;
        float dub = u1 - (float)gb;
        float ra = ((unsigned)ga < 32u) ? __expf(-0.5f * dua * dua) : 0.f;
        float rb = ((unsigned)gb < 32u) ? __expf(-0.5f * dub * dub) : 0.f;
        __half2 rha = __float2half2_rn(ra);
        __half2 rhb = __float2half2_rn(rb);
        int gca = min(max(ga, 0), 31) * 5;
        int gcb = min(max(gb, 0), 31) * 5;
        #pragma unroll
        for (int p = 0; p < 4; p++) {
            acc0[p] = __hfma2(rha, w2_s[gca + p], acc0[p]);
            acc1[p] = __hfma2(rhb, w2_s[gcb + p], acc1[p]);
        }
    }

    #pragma unroll
    for (int p = 0; p < 4; p++) {
        __half2 lo = __lows2half2(acc0[p], acc1[p]);    // head 2p:   (k, k+1)
        __half2 hi = __highs2half2(acc0[p], acc1[p]);   // head 2p+1: (k, k+1)
        size_t i0 = ((size_t)(b * NH + 2 * p)     * NN + q) * NN + k;
        size_t i1 = ((size_t)(b * NH + 2 * p + 1) * NN + q) * NN + k;
        *(__half2*)&bias[i0] = lo;
        *(__half2*)&bias[i1] = hi;
    }
}

// ---------------------------------------------------------------------------
// FP16 tensor-core flash attention (unchanged structure; half ctx output)
// ---------------------------------------------------------------------------
#define KVSTRIDE 40   // halves per row (32 + 8 pad)

__global__ __launch_bounds__(256)
void attn_kernel(const __half* __restrict__ qkv,
                 const __half* __restrict__ bias,
                 __half* __restrict__ ctx) {
    const int qt = blockIdx.x;
    const int h  = blockIdx.y;
    const int b  = blockIdx.z;
    const int q0 = qt * 128;
    const int t  = threadIdx.x;
    const int wid  = t >> 5;
    const int lane = t & 31;
    const int g  = lane >> 2;
    const int tt = lane & 3;
    const int wr = wid * 16;

    __shared__ __align__(16) __half Qs[128 * KVSTRIDE];
    __shared__ __align__(16) __half Ks[2 * 64 * KVSTRIDE];
    __shared__ __align__(16) __half Vs[2 * 64 * KVSTRIDE];

    #pragma unroll
    for (int r = 0; r < 2; r++) {
        int id = t * 2 + r;
        int row = id >> 2, seg = id & 3;
        cp16(&Qs[row * KVSTRIDE + seg * 8],
             qkv + (size_t)(b * NN + q0 + row) * 768 + h * HD + seg * 8);
    }
    {
        int row = t >> 2, seg = t & 3;
        size_t src = (size_t)(b * NN + row) * 768 + h * HD + seg * 8;
        cp16(&Ks[row * KVSTRIDE + seg * 8], qkv + src + 256);
        cp16(&Vs[row * KVSTRIDE + seg * 8], qkv + src + 512);
    }
    CP_COMMIT();

    float m0 = -1e30f, m1 = -1e30f, l0 = 0.f, l1 = 0.f;
    float O[4][4] = {};
    uint32_t qa[2][4];
    bool qloaded = false;

    const __half* bptr0 = bias + ((size_t)(b * NH + h) * NN + (q0 + wr + g)) * NN;
    const __half* bptr1 = bptr0 + 8 * (size_t)NN;

    for (int kt = 0; kt < 8; kt++) {
        int buf = kt & 1;
        if (kt + 1 < 8) {
            int nb = (kt + 1) & 1;
            int k0n = (kt + 1) * 64;
            int row = t >> 2, seg = t & 3;
            size_t src = (size_t)(b * NN + k0n + row) * 768 + h * HD + seg * 8;
            cp16(&Ks[nb * 64 * KVSTRIDE + row * KVSTRIDE + seg * 8], qkv + src + 256);
            cp16(&Vs[nb * 64 * KVSTRIDE + row * KVSTRIDE + seg * 8], qkv + src + 512);
            CP_COMMIT();
            asm volatile("cp.async.wait_group 1;");
        } else {
            asm volatile("cp.async.wait_group 0;");
        }
        __syncthreads();

        if (!qloaded) {
            qloaded = true;
            #pragma unroll
            for (int ks = 0; ks < 2; ks++) {
                uint32_t a = smem_u32(&Qs[(wr + (lane & 15)) * KVSTRIDE + ks * 16 + 8 * (lane >> 4)]);
                LDSM_X4(qa[ks][0], qa[ks][1], qa[ks][2], qa[ks][3], a);
            }
        }

        const __half* Kb = Ks + buf * 64 * KVSTRIDE;
        const __half* Vb = Vs + buf * 64 * KVSTRIDE;

        float S[8][4];
        #pragma unroll
        for (int nt = 0; nt < 8; nt++) { S[nt][0] = S[nt][1] = S[nt][2] = S[nt][3] = 0.f; }

        #pragma unroll
        for (int ks = 0; ks < 2; ks++) {
            #pragma unroll
            for (int p = 0; p < 4; p++) {
                int rowk = 16 * p + 8 * (lane >> 4) + (lane & 7);
                int colk = ks * 16 + 8 * ((lane >> 3) & 1);
                uint32_t b0, b1, b2, b3;
                LDSM_X4(b0, b1, b2, b3, smem_u32(&Kb[rowk * KVSTRIDE + colk]));
                mma_f16(S[2 * p],     qa[ks], b0, b1);
                mma_f16(S[2 * p + 1], qa[ks], b2, b3);
            }
        }

        int k0 = kt * 64;
        #pragma unroll
        for (int nt = 0; nt < 8; nt++) {
            float2 f0 = __half22float2(*(const __half2*)(bptr0 + k0 + nt * 8 + 2 * tt));
            float2 f1 = __half22float2(*(const __half2*)(bptr1 + k0 + nt * 8 + 2 * tt));
            S[nt][0] += f0.x; S[nt][1] += f0.y;
            S[nt][2] += f1.x; S[nt][3] += f1.y;
        }

        float mx0 = -1e30f, mx1 = -1e30f;
        #pragma unroll
        for (int nt = 0; nt < 8; nt++) {
            mx0 = fmaxf(mx0, fmaxf(S[nt][0], S[nt][1]));
            mx1 = fmaxf(mx1, fmaxf(S[nt][2], S[nt][3]));
        }
        #pragma unroll
        for (int off = 1; off <= 2; off <<= 1) {
            mx0 = fmaxf(mx0, __shfl_xor_sync(0xffffffffu, mx0, off));
            mx1 = fmaxf(mx1, __shfl_xor_sync(0xffffffffu, mx1, off));
        }
        float mn0 = fmaxf(m0, mx0), mn1 = fmaxf(m1, mx1);
        float sc0 = __expf(m0 - mn0), sc1 = __expf(m1 - mn1);
        float ls0 = 0.f, ls1 = 0.f;
        #pragma unroll
        for (int nt = 0; nt < 8; nt++) {
            S[nt][0] = __expf(S[nt][0] - mn0);
            S[nt][1] = __expf(S[nt][1] - mn0);
            S[nt][2] = __expf(S[nt][2] - mn1);
            S[nt][3] = __expf(S[nt][3] - mn1);
            ls0 += S[nt][0] + S[nt][1];
            ls1 += S[nt][2] + S[nt][3];
        }
        #pragma unroll
        for (int off = 1; off <= 2; off <<= 1) {
            ls0 += __shfl_xor_sync(0xffffffffu, ls0, off);
            ls1 += __shfl_xor_sync(0xffffffffu, ls1, off);
        }
        m0 = mn0; m1 = mn1;
        l0 = l0 * sc0 + ls0;
        l1 = l1 * sc1 + ls1;
        #pragma unroll
        for (int nt = 0; nt < 4; nt++) {
            O[nt][0] *= sc0; O[nt][1] *= sc0;
            O[nt][2] *= sc1; O[nt][3] *= sc1;
        }

        #pragma unroll
        for (int j = 0; j < 4; j++) {
            uint32_t pa[4];
            pa[0] = packh2(S[2 * j][0],     S[2 * j][1]);
            pa[1] = packh2(S[2 * j][2],     S[2 * j][3]);
            pa[2] = packh2(S[2 * j + 1][0], S[2 * j + 1][1]);
            pa[3] = packh2(S[2 * j + 1][2], S[2 * j + 1][3]);
            #pragma unroll
            for (int q2 = 0; q2 < 2; q2++) {
                int rowv = j * 16 + (lane & 7) + 8 * ((lane >> 3) & 1);
                int colv = q2 * 16 + 8 * (lane >> 4);
                uint32_t b0, b1, b2, b3;
                LDSM_X4_T(b0, b1, b2, b3, smem_u32(&Vb[rowv * KVSTRIDE + colv]));
                mma_f16(O[2 * q2],     pa, b0, b1);
                mma_f16(O[2 * q2 + 1], pa, b2, b3);
            }
        }
        __syncthreads();
    }

    float inv0 = 1.0f / l0, inv1 = 1.0f / l1;
    #pragma unroll
    for (int nt = 0; nt < 4; nt++) {
        int col = h * HD + nt * 8 + 2 * tt;
        *(__half2*)&ctx[(size_t)(b * NN + q0 + wr + g)     * DIM + col] =
            __floats2half2_rn(O[nt][0] * inv0, O[nt][1] * inv0);
        *(__half2*)&ctx[(size_t)(b * NN + q0 + wr + g + 8) * DIM + col] =
            __floats2half2_rn(O[nt][2] * inv1, O[nt][3] * inv1);
    }
}

// ---------------------------------------------------------------------------
// FP16 tensor-core GEMM: C = A[M,K] @ Bw[Nn,K]^T + bias (+gelu)(+res)
// Block 128x128x64, 256 threads (8 warps, 2x4), warp tile 64x32.
// mma.m16n8k16.f16 with f32 accum, ldmatrix fragments, cp.async dbl-buffered.
// OUTH: half output; qscale applied to cols < DIM (Q pre-scale for qkv GEMM).
// ---------------------------------------------------------------------------
#define HSTRIDE 72                 // halves per smem row (64 + 8 pad) = 144B
#define HTILE   (128 * HSTRIDE)    // halves per matrix per buffer

template<bool GELU, bool RES, bool OUTH>
__global__ __launch_bounds__(256)
void h16_gemm(const __half* __restrict__ A,
              const __half* __restrict__ Bw,
              const float* __restrict__ bias,
              const float* __restrict__ res,
              void* __restrict__ Cv,
              int Nn, int K, float qscale) {
    extern __shared__ __half hsm[];
    __half* As = hsm;                // [2][128][72]
    __half* Bs = hsm + 2 * HTILE;    // [2][128][72]

    const int t    = threadIdx.x;
    const int bm   = blockIdx.x * 128;
    const int bn   = blockIdx.y * 128;
    const int wid  = t >> 5;
    const int lane = t & 31;
    const int wm   = (wid >> 2) * 64;
    const int wn   = (wid & 3) * 32;
    const int g    = lane >> 2;
    const int tt   = lane & 3;

    float acc[4][4][4];
    #pragma unroll
    for (int i = 0; i < 4; i++)
        #pragma unroll
        for (int j = 0; j < 4; j++)
            #pragma unroll
            for (int c = 0; c < 4; c++) acc[i][j][c] = 0.f;

    const int niter = K >> 6;

    // prologue: tile 0 (128 rows x 8 segs of 16B per matrix; 4 tasks each/thread)
    #pragma unroll
    for (int i = 0; i < 4; i++) {
        int task = t + i * 256;
        int row = task >> 3, seg = task & 7;
        cp16(&As[row * HSTRIDE + seg * 8], A  + (size_t)(bm + row) * K + seg * 8);
        cp16(&Bs[row * HSTRIDE + seg * 8], Bw + (size_t)(bn + row) * K + seg * 8);
    }
    CP_COMMIT();

    for (int it = 0; it < niter; it++) {
        if (it + 1 < niter) {
            int buf = (it + 1) & 1;
            int k0  = (it + 1) * 64;
            #pragma unroll
            for (int i = 0; i < 4; i++) {
                int task = t + i * 256;
                int row = task >> 3, seg = task & 7;
                cp16(&As[buf * HTILE + row * HSTRIDE + seg * 8],
                     A  + (size_t)(bm + row) * K + k0 + seg * 8);
                cp16(&Bs[buf * HTILE + row * HSTRIDE + seg * 8],
                     Bw + (size_t)(bn + row) * K + k0 + seg * 8);
            }
            CP_COMMIT();
            asm volatile("cp.async.wait_group 1;");
        } else {
            asm volatile("cp.async.wait_group 0;");
        }
        __syncthreads();

        const __half* Ab = As + (it & 1) * HTILE;
        const __half* Bb = Bs + (it & 1) * HTILE;

        #pragma unroll
        for (int ks = 0; ks < 4; ks++) {
            uint32_t af[4][4];
            #pragma unroll
            for (int mt = 0; mt < 4; mt++) {
                uint32_t a = smem_u32(&Ab[(wm + mt * 16 + (lane & 15)) * HSTRIDE
                                          + ks * 16 + 8 * (lane >> 4)]);
                LDSM_X4(af[mt][0], af[mt][1], af[mt][2], af[mt][3], a);
            }
            #pragma unroll
            for (int pp = 0; pp < 2; pp++) {
                int rowk = wn + pp * 16 + 8 * (lane >> 4) + (lane & 7);
                int colk = ks * 16 + 8 * ((lane >> 3) & 1);
                uint32_t b0, b1, b2, b3;
                LDSM_X4(b0, b1, b2, b3, smem_u32(&Bb[rowk * HSTRIDE + colk]));
                #pragma unroll
                for (int mt = 0; mt < 4; mt++) {
                    mma_f16(acc[mt][2 * pp],     af[mt], b0, b1);
                    mma_f16(acc[mt][2 * pp + 1], af[mt], b2, b3);
                }
            }
        }
        __syncthreads();
    }

    // epilogue: c0:(g,2tt) c1:(g,2tt+1) c2:(g+8,2tt) c3:(g+8,2tt+1)
    #pragma unroll
    for (int mt = 0; mt < 4; mt++) {
        #pragma unroll
        for (int nt = 0; nt < 4; nt++) {
            int row0 = bm + wm + mt * 16 + g;
            int col  = bn + wn + nt * 8 + 2 * tt;
            float b0 = bias[col], b1 = bias[col + 1];

            float v00 = acc[mt][nt][0] + b0;
            float v01 = acc[mt][nt][1] + b1;
            float v10 = acc[mt][nt][2] + b0;
            float v11 = acc[mt][nt][3] + b1;
            if (GELU) {
                v00 = 0.5f * v00 * (1.0f + erff(v00 * 0.70710678118654752f));
                v01 = 0.5f * v01 * (1.0f + erff(v01 * 0.70710678118654752f));
                v10 = 0.5f * v10 * (1.0f + erff(v10 * 0.70710678118654752f));
                v11 = 0.5f * v11 * (1.0f + erff(v11 * 0.70710678118654752f));
            }
            if (RES) {
                float2 r0 = *(const float2*)&res[(size_t)row0 * Nn + col];
                float2 r1 = *(const float2*)&res[(size_t)(row0 + 8) * Nn + col];
                v00 += r0.x; v01 += r0.y;
                v10 += r1.x; v11 += r1.y;
            }
            if (OUTH) {
                float s = (col < DIM) ? qscale : 1.0f;
                __half* C = (__half*)Cv;
                *(__half2*)&C[(size_t)row0 * Nn + col]       = __floats2half2_rn(v00 * s, v01 * s);
                *(__half2*)&C[(size_t)(row0 + 8) * Nn + col] = __floats2half2_rn(v10 * s, v11 * s);
            } else {
                float* C = (float*)Cv;
                float2 o0; o0.x = v00; o0.y = v01;
                float2 o1; o1.x = v10; o1.y = v11;
                *(float2*)&C[(size_t)row0 * Nn + col]       = o0;
                *(float2*)&C[(size_t)(row0 + 8) * Nn + col] = o1;
            }
        }
    }
}

#define GEMM_SMEM (4 * HTILE * sizeof(__half))   // 73728 B

// ---------------------------------------------------------------------------
// launch
// ---------------------------------------------------------------------------
extern "C" void kernel_launch(void* const* d_in, const int* in_sizes, int n_in,
                              void* d_out, int out_size) {
    const float* x    = (const float*)d_in[0];
    const int*   dm   = (const int*)  d_in[2];
    const float* d3   = (const float*)d_in[3];
    const float* n1g  = (const float*)d_in[4];
    const float* n1b  = (const float*)d_in[5];
    const float* ipw  = (const float*)d_in[6];
    const float* ipb  = (const float*)d_in[7];
    const float* opw  = (const float*)d_in[8];
    const float* opb  = (const float*)d_in[9];
    const float* demb = (const float*)d_in[10];
    const float* rbfw = (const float*)d_in[11];
    const float* rbfb = (const float*)d_in[12];
    const float* n2g  = (const float*)d_in[13];
    const float* n2b  = (const float*)d_in[14];
    const float* w1   = (const float*)d_in[15];
    const float* b1   = (const float*)d_in[16];
    const float* w2   = (const float*)d_in[17];
    const float* b2   = (const float*)d_in[18];
    float* out = (float*)d_out;

    float* scratch = nullptr;
    cudaGetSymbolAddress((void**)&scratch, g_scratch);
    __half* bias  = (__half*)(scratch + OFF_BIAS);
    float*  hs32  = scratch + OFF_HS32;
    __half* hsh   = (__half*)(scratch + OFF_HSH);
    __half* qkv   = (__half*)(scratch + OFF_QKV);
    __half* ctxh  = (__half*)(scratch + OFF_CTXH);
    float*  hatt  = scratch + OFF_HATT;
    __half* h2h   = (__half*)(scratch + OFF_H2H);
    __half* f1h   = (__half*)(scratch + OFF_F1H);
    __half* wh    = (__half*)(scratch + OFF_WH);
    __half* ipw_h = wh + WH_IPW;
    __half* opw_h = wh + WH_OPW;
    __half* w1_h  = wh + WH_W1;
    __half* w2_h  = wh + WH_W2;

    static bool attr_done = false;
    if (!attr_done) {
        cudaFuncSetAttribute(h16_gemm<false, false, true >, cudaFuncAttributeMaxDynamicSharedMemorySize, GEMM_SMEM);
        cudaFuncSetAttribute(h16_gemm<false, true,  false>, cudaFuncAttributeMaxDynamicSharedMemorySize, GEMM_SMEM);
        cudaFuncSetAttribute(h16_gemm<true,  false, true >, cudaFuncAttributeMaxDynamicSharedMemorySize, GEMM_SMEM);
        attr_done = true;
    }

    const float qscale = 0.17677669529663687f;  // 1/sqrt(32)

    // 0. weights -> half (once per call; stream-ordered before GEMMs)
    convert_w<<<1536, 256>>>(ipw, opw, w1, w2, (__half2*)wh);
    // 1. h = LN1(x): half for GEMM + f32 residual
    ln_kernel<<<ROWS, 256>>>(x, n1g, n1b, hsh, hs32);
    // 2. qkv = h @ in_proj_w^T + b  (half out, Q pre-scaled)
    h16_gemm<false, false, true><<<dim3(ROWS / 128, 768 / 128), 256, GEMM_SMEM>>>(
        hsh, ipw_h, ipb, nullptr, qkv, 768, 256, qscale);
    // 3. bias[b,h,q,k] (half, windowed gaussian)
    bias_kernel<<<ROWS, 256>>>(dm, d3, demb, rbfw, rbfb, bias);
    // 4. attention -> ctx half
    attn_kernel<<<dim3(NN / 128, NH, BB), 256>>>(qkv, bias, ctxh);
    // 5. hatt = ctx @ out_proj^T + b + h   (f32 out)
    h16_gemm<false, true, false><<<dim3(ROWS / 128, 256 / 128), 256, GEMM_SMEM>>>(
        ctxh, opw_h, opb, hs32, hatt, 256, 256, 1.0f);
    // 6. h2 = LN2(hatt)  (half only)
    ln_kernel<<<ROWS, 256>>>(hatt, n2g, n2b, h2h, nullptr);
    // 7. f1 = gelu(h2 @ w1^T + b1)  (half out)
    h16_gemm<true, false, true><<<dim3(ROWS / 128, 1024 / 128), 256, GEMM_SMEM>>>(
        h2h, w1_h, b1, nullptr, f1h, 1024, 256, 1.0f);
    // 8. out = f1 @ w2^T + b2 + hatt  (f32 out)
    h16_gemm<false, true, false><<<dim3(ROWS / 128, 256 / 128), 256, GEMM_SMEM>>>(
        f1h, w2_h, b2, hatt, out, 256, 1024, 1.0f);
}